// round 1
// baseline (speedup 1.0000x reference)
#include <cuda_runtime.h>
#include <math.h>

#define NB   4
#define NTOK 2304
#define DIM  256
#define AGH  512

// ---------------- scratch (device globals; no allocation allowed) ----------------
__device__ float g_h1[NB*NTOK*AGH];
__device__ float g_lf[NB*NTOK];
__device__ float g_maskf[NB*NTOK];
__device__ int   g_idx[NB*NTOK];
__device__ int   g_S[NB];
__device__ float g_Xi[NB*NTOK*DIM];
__device__ float g_Xv[NB*NTOK*DIM];
__device__ float g_xn[NB*NTOK*DIM];
__device__ float g_qkv[NB*NTOK*3*DIM];
__device__ float g_attn[NB*NTOK*DIM];
__device__ float g_x1[NB*NTOK*DIM];
__device__ float g_hff[NB*NTOK*4*DIM];
__device__ float g_mix[NB*NTOK*DIM];

// ---------------- agent GEMM: h1[p][m] = silu(sum_c X[p][c]*aw1[m][c] + ab1[m]) --
// X[p][c] = c<256 ? f_ir[b][c][n] : f_vis[b][c-256][n],  p = b*NTOK + n
__global__ void agent_gemm_kernel(const float* __restrict__ f_ir,
                                  const float* __restrict__ f_vis,
                                  const float* __restrict__ aw1,
                                  const float* __restrict__ ab1)
{
    __shared__ float As[16][68];
    __shared__ float Ws[16][68];
    int tid = threadIdx.x;
    int tx = tid & 15, ty = tid >> 4;
    int p0 = blockIdx.x * 64;
    int m0 = blockIdx.y * 64;
    int b = p0 / NTOK;               // tiles never straddle batches (2304 % 64 == 0)
    int nbase = p0 - b * NTOK;
    float acc[4][4];
#pragma unroll
    for (int i = 0; i < 4; i++)
#pragma unroll
        for (int j = 0; j < 4; j++) acc[i][j] = 0.f;

    for (int k0 = 0; k0 < 512; k0 += 16) {
#pragma unroll
        for (int it = 0; it < 4; it++) {
            int idx = tid + it * 256;
            {   // A tile: coalesced along n
                int r = idx & 63, kk = idx >> 6;
                int c = k0 + kk;
                float v = (c < 256)
                    ? f_ir [((size_t)b*256 +  c       )*NTOK + nbase + r]
                    : f_vis[((size_t)b*256 + (c - 256))*NTOK + nbase + r];
                As[kk][r] = v;
            }
            {   // W tile: coalesced along k
                int r = idx >> 4, kk = idx & 15;
                Ws[kk][r] = aw1[(size_t)(m0 + r)*512 + k0 + kk];
            }
        }
        __syncthreads();
#pragma unroll
        for (int kk = 0; kk < 16; kk++) {
            float4 a4 = *(const float4*)&As[kk][ty*4];
            float4 w4 = *(const float4*)&Ws[kk][tx*4];
            float av[4] = {a4.x, a4.y, a4.z, a4.w};
            float wv[4] = {w4.x, w4.y, w4.z, w4.w};
#pragma unroll
            for (int i = 0; i < 4; i++)
#pragma unroll
                for (int j = 0; j < 4; j++) acc[i][j] += av[i] * wv[j];
        }
        __syncthreads();
    }
#pragma unroll
    for (int i = 0; i < 4; i++) {
        int p = p0 + ty*4 + i;
#pragma unroll
        for (int j = 0; j < 4; j++) {
            int m = m0 + tx*4 + j;
            float v = acc[i][j] + ab1[m];
            v = v / (1.f + expf(-v));          // silu
            g_h1[(size_t)p*AGH + m] = v;
        }
    }
}

// ---------------- logits: lf[p] = h1[p]·aw2 + ab2 (warp per pixel) --------------
__global__ void logits_kernel(const float* __restrict__ aw2,
                              const float* __restrict__ ab2)
{
    int p = blockIdx.x * 8 + (threadIdx.x >> 5);
    int lane = threadIdx.x & 31;
    const float* h = g_h1 + (size_t)p * AGH;
    float s = 0.f;
#pragma unroll
    for (int j = 0; j < 16; j++) s += h[lane + 32*j] * aw2[lane + 32*j];
#pragma unroll
    for (int o = 16; o > 0; o >>= 1) s += __shfl_xor_sync(0xffffffffu, s, o);
    if (lane == 0) g_lf[p] = s + ab2[0];
}

// ---------------- selection + top-64 fallback + compaction (block per batch) ----
__global__ void select_kernel()
{
    __shared__ float vals[NTOK];
    __shared__ int   sels[NTOK];
    __shared__ int   cnts[256];
    __shared__ float rv[256];
    __shared__ int   ri[256];
    __shared__ int   offs[257];
    int b = blockIdx.x, tid = threadIdx.x;

    int localc = 0;
    for (int n = tid; n < NTOK; n += 256) {
        float v = g_lf[b*NTOK + n];
        vals[n] = v;
        int s = (v > 0.f) ? 1 : 0;
        sels[n] = s;
        g_maskf[b*NTOK + n] = s ? 1.f : 0.f;
        localc += s;
    }
    cnts[tid] = localc;
    __syncthreads();
    for (int o = 128; o > 0; o >>= 1) {
        if (tid < o) cnts[tid] += cnts[tid + o];
        __syncthreads();
    }
    int count = cnts[0];
    __syncthreads();

    if (count < 64) {   // top-64 fallback (iterative argmax, lower index on ties)
        for (int n = tid; n < NTOK; n += 256) sels[n] = 0;
        __syncthreads();
        for (int iter = 0; iter < 64; iter++) {
            float bv = -1e38f; int bi = NTOK;
            for (int n = tid; n < NTOK; n += 256)
                if (!sels[n] && vals[n] > bv) { bv = vals[n]; bi = n; }
            rv[tid] = bv; ri[tid] = bi;
            __syncthreads();
            for (int o = 128; o > 0; o >>= 1) {
                if (tid < o) {
                    if (rv[tid+o] > rv[tid] ||
                        (rv[tid+o] == rv[tid] && ri[tid+o] < ri[tid])) {
                        rv[tid] = rv[tid+o]; ri[tid] = ri[tid+o];
                    }
                }
                __syncthreads();
            }
            if (tid == 0) sels[ri[0]] = 1;
            __syncthreads();
        }
    }

    // compaction: contiguous chunk of 9 per thread, ascending order preserved
    int base = tid * 9;
    int lc = 0;
    for (int k = 0; k < 9; k++) lc += sels[base + k];
    cnts[tid] = lc;
    __syncthreads();
    if (tid == 0) {
        int run = 0;
        for (int i = 0; i < 256; i++) { offs[i] = run; run += cnts[i]; }
        offs[256] = run;
        g_S[b] = run;
    }
    __syncthreads();
    int pos = offs[tid];
    for (int k = 0; k < 9; k++)
        if (sels[base + k]) g_idx[b*NTOK + pos++] = base + k;
}

// ---------------- gather compacted tokens: X[b][s][c] = f[b][c][idx[s]] --------
__global__ void gather_kernel(const float* __restrict__ f_ir,
                              const float* __restrict__ f_vis)
{
    int b = blockIdx.y, s = blockIdx.x;
    if (s >= g_S[b]) return;
    int n = g_idx[b*NTOK + s];
    int c = threadIdx.x;
    g_Xi[((size_t)b*NTOK + s)*DIM + c] = f_ir [((size_t)b*DIM + c)*NTOK + n];
    g_Xv[((size_t)b*NTOK + s)*DIM + c] = f_vis[((size_t)b*DIM + c)*NTOK + n];
}

// ---------------- LayerNorm over 256 dims, warp per token ----------------------
__global__ void ln_kernel(const float* __restrict__ X,
                          const float* __restrict__ g,
                          const float* __restrict__ bta,
                          float* __restrict__ O)
{
    int b = blockIdx.y;
    int t = blockIdx.x * 8 + (threadIdx.x >> 5);
    if (t >= g_S[b]) return;
    int lane = threadIdx.x & 31;
    const float* x = X + ((size_t)b*NTOK + t)*DIM;
    float v[8];
    float s = 0.f;
#pragma unroll
    for (int j = 0; j < 8; j++) { v[j] = x[lane + 32*j]; s += v[j]; }
#pragma unroll
    for (int o = 16; o > 0; o >>= 1) s += __shfl_xor_sync(0xffffffffu, s, o);
    float mean = s * (1.f/256.f);
    float vs = 0.f;
#pragma unroll
    for (int j = 0; j < 8; j++) { float d = v[j] - mean; vs += d*d; }
#pragma unroll
    for (int o = 16; o > 0; o >>= 1) vs += __shfl_xor_sync(0xffffffffu, vs, o);
    float rstd = rsqrtf(vs * (1.f/256.f) + 1e-5f);
    float* o = O + ((size_t)b*NTOK + t)*DIM;
#pragma unroll
    for (int j = 0; j < 8; j++) {
        int c = lane + 32*j;
        o[c] = (v[j] - mean) * rstd * g[c] + bta[c];
    }
}

// ---------------- generic mixer GEMM: C = [act](A·W^T + bias) [+R] [+=] --------
template<int ACT, bool RES, bool ACC>
__global__ void mixer_gemm(const float* __restrict__ A, const float* __restrict__ W,
                           const float* __restrict__ bias, const float* __restrict__ R,
                           float* __restrict__ C, int K, int M)
{
    int b = blockIdx.z;
    int S = g_S[b];
    int row0 = blockIdx.x * 64;
    if (row0 >= S) return;
    int m0 = blockIdx.y * 64;
    const float* Ab = A + (size_t)b*NTOK*K;
    float*       Cb = C + (size_t)b*NTOK*M;
    const float* Rb = RES ? (R + (size_t)b*NTOK*M) : nullptr;

    __shared__ float As[16][68];
    __shared__ float Ws[16][68];
    int tid = threadIdx.x;
    int tx = tid & 15, ty = tid >> 4;
    float acc[4][4];
#pragma unroll
    for (int i = 0; i < 4; i++)
#pragma unroll
        for (int j = 0; j < 4; j++) acc[i][j] = 0.f;

    for (int k0 = 0; k0 < K; k0 += 16) {
#pragma unroll
        for (int it = 0; it < 4; it++) {
            int idx = tid + it * 256;
            int r = idx >> 4, kk = idx & 15;
            int row = row0 + r;
            As[kk][r] = (row < S) ? Ab[(size_t)row*K + k0 + kk] : 0.f;
            Ws[kk][r] = W[(size_t)(m0 + r)*K + k0 + kk];
        }
        __syncthreads();
#pragma unroll
        for (int kk = 0; kk < 16; kk++) {
            float4 a4 = *(const float4*)&As[kk][ty*4];
            float4 w4 = *(const float4*)&Ws[kk][tx*4];
            float av[4] = {a4.x, a4.y, a4.z, a4.w};
            float wv[4] = {w4.x, w4.y, w4.z, w4.w};
#pragma unroll
            for (int i = 0; i < 4; i++)
#pragma unroll
                for (int j = 0; j < 4; j++) acc[i][j] += av[i] * wv[j];
        }
        __syncthreads();
    }
#pragma unroll
    for (int i = 0; i < 4; i++) {
        int row = row0 + ty*4 + i;
        if (row >= S) continue;
#pragma unroll
        for (int j = 0; j < 4; j++) {
            int m = m0 + tx*4 + j;
            float v = acc[i][j] + bias[m];
            if (ACT == 1) v = 0.5f * v * (1.f + erff(v * 0.70710678118654752f)); // exact gelu
            if (RES) v += Rb[(size_t)row*M + m];
            if (ACC) Cb[(size_t)row*M + m] += v;
            else     Cb[(size_t)row*M + m]  = v;
        }
    }
}

// ---------------- flash attention over compacted tokens (dh=64, 4 heads) -------
__global__ void flash_kernel()
{
    extern __shared__ float sm[];
    float* Qs = sm;               // [d][r], stride 68
    float* Ks = sm + 64*68;       // [d][r]
    float* Vs = sm + 2*64*68;     // [k][d]
    float* Ps = sm + 3*64*68;     // [k][q]
    int b = blockIdx.z;
    int h = blockIdx.y;
    int S = g_S[b];
    int qb = blockIdx.x * 64;
    if (qb >= S) return;
    int tid = threadIdx.x;
    int tx = tid & 15, ty = tid >> 4;
    const float* qkvb = g_qkv + (size_t)b * NTOK * 768;

#pragma unroll
    for (int it = 0; it < 16; it++) {
        int idx = tid + it * 256;
        int r = idx >> 6, d = idx & 63;
        int t = qb + r;
        Qs[d*68 + r] = (t < S) ? qkvb[(size_t)t*768 + h*64 + d] : 0.f;
    }

    float m_i[4], l_i[4], oa[4][4];
#pragma unroll
    for (int i = 0; i < 4; i++) {
        m_i[i] = -1e30f; l_i[i] = 0.f;
#pragma unroll
        for (int j = 0; j < 4; j++) oa[i][j] = 0.f;
    }

    for (int kb = 0; kb < S; kb += 64) {
        __syncthreads();
#pragma unroll
        for (int it = 0; it < 16; it++) {
            int idx = tid + it * 256;
            int r = idx >> 6, d = idx & 63;
            int t = kb + r;
            bool ok = (t < S);
            Ks[d*68 + r] = ok ? qkvb[(size_t)t*768 + 256 + h*64 + d] : 0.f;
            Vs[r*68 + d] = ok ? qkvb[(size_t)t*768 + 512 + h*64 + d] : 0.f;
        }
        __syncthreads();

        float sc[4][4];
#pragma unroll
        for (int i = 0; i < 4; i++)
#pragma unroll
            for (int j = 0; j < 4; j++) sc[i][j] = 0.f;
#pragma unroll 8
        for (int d = 0; d < 64; d++) {
            float4 q4 = *(const float4*)(Qs + d*68 + ty*4);
            float4 k4 = *(const float4*)(Ks + d*68 + tx*4);
            float qv[4] = {q4.x, q4.y, q4.z, q4.w};
            float kv[4] = {k4.x, k4.y, k4.z, k4.w};
#pragma unroll
            for (int i = 0; i < 4; i++)
#pragma unroll
                for (int j = 0; j < 4; j++) sc[i][j] += qv[i] * kv[j];
        }
#pragma unroll
        for (int i = 0; i < 4; i++)
#pragma unroll
            for (int j = 0; j < 4; j++) {
                sc[i][j] *= 0.125f;                       // 1/sqrt(64)
                if (kb + tx*4 + j >= S) sc[i][j] = -1e30f;
            }
#pragma unroll
        for (int i = 0; i < 4; i++) {
            float rm = fmaxf(fmaxf(sc[i][0], sc[i][1]), fmaxf(sc[i][2], sc[i][3]));
#pragma unroll
            for (int o = 8; o > 0; o >>= 1) rm = fmaxf(rm, __shfl_xor_sync(0xffffffffu, rm, o));
            float mn = fmaxf(m_i[i], rm);
            float rs = 0.f;
#pragma unroll
            for (int j = 0; j < 4; j++) {
                float p = expf(sc[i][j] - mn);
                sc[i][j] = p; rs += p;
            }
#pragma unroll
            for (int o = 8; o > 0; o >>= 1) rs += __shfl_xor_sync(0xffffffffu, rs, o);
            float al = expf(m_i[i] - mn);
            l_i[i] = l_i[i] * al + rs;
            m_i[i] = mn;
#pragma unroll
            for (int j = 0; j < 4; j++) oa[i][j] *= al;
        }
#pragma unroll
        for (int i = 0; i < 4; i++)
#pragma unroll
            for (int j = 0; j < 4; j++)
                Ps[(tx*4 + j)*68 + (ty*4 + i)] = sc[i][j];
        __syncthreads();
#pragma unroll 8
        for (int kk = 0; kk < 64; kk++) {
            float4 p4 = *(const float4*)(Ps + kk*68 + ty*4);
            float4 v4 = *(const float4*)(Vs + kk*68 + tx*4);
            float pv[4] = {p4.x, p4.y, p4.z, p4.w};
            float vv[4] = {v4.x, v4.y, v4.z, v4.w};
#pragma unroll
            for (int i = 0; i < 4; i++)
#pragma unroll
                for (int j = 0; j < 4; j++) oa[i][j] += pv[i] * vv[j];
        }
    }
    float* ab = g_attn + (size_t)b*NTOK*DIM;
#pragma unroll
    for (int i = 0; i < 4; i++) {
        int t = qb + ty*4 + i;
        if (t < S) {
            float inv = 1.f / l_i[i];
            float4 o4 = make_float4(oa[i][0]*inv, oa[i][1]*inv, oa[i][2]*inv, oa[i][3]*inv);
            *(float4*)(ab + (size_t)t*DIM + h*64 + tx*4) = o4;
        }
    }
}

// ---------------- base canvas + final scatter ----------------------------------
__global__ void base_kernel(const float* __restrict__ a, const float* __restrict__ c,
                            float* __restrict__ out)
{
    int i = blockIdx.x * 256 + threadIdx.x;
    out[i] = a[i] + c[i];
}

__global__ void scatter_kernel(float* __restrict__ out)
{
    int b = blockIdx.y, s = blockIdx.x;
    if (s >= g_S[b]) return;
    int n = g_idx[b*NTOK + s];
    int c = threadIdx.x;
    float v = g_mix[((size_t)b*NTOK + s)*DIM + c] * g_maskf[b*NTOK + n];
    out[((size_t)b*DIM + c)*NTOK + n] = v;
}

// ---------------- host ----------------------------------------------------------
#define GETSYM(ptr, sym) cudaGetSymbolAddress((void**)&(ptr), sym)

extern "C" void kernel_launch(void* const* d_in, const int* in_sizes, int n_in,
                              void* d_out, int out_size)
{
    const float* f_ir  = (const float*)d_in[0];
    const float* f_vis = (const float*)d_in[1];
    const float* aw1   = (const float*)d_in[2];
    const float* ab1   = (const float*)d_in[3];
    const float* aw2   = (const float*)d_in[4];
    const float* ab2   = (const float*)d_in[5];
    const float* P[20];
    for (int i = 0; i < 20; i++) P[i] = (const float*)d_in[6 + i];
    float* out = (float*)d_out;

    float *p_Xi, *p_Xv, *p_xn, *p_qkv, *p_attn, *p_x1, *p_hff, *p_mix;
    GETSYM(p_Xi, g_Xi);   GETSYM(p_Xv, g_Xv);   GETSYM(p_xn, g_xn);
    GETSYM(p_qkv, g_qkv); GETSYM(p_attn, g_attn); GETSYM(p_x1, g_x1);
    GETSYM(p_hff, g_hff); GETSYM(p_mix, g_mix);

    cudaFuncSetAttribute(flash_kernel, cudaFuncAttributeMaxDynamicSharedMemorySize,
                         4*64*68*(int)sizeof(float));

    agent_gemm_kernel<<<dim3(144, 8), 256>>>(f_ir, f_vis, aw1, ab1);
    logits_kernel<<<1152, 256>>>(aw2, ab2);
    select_kernel<<<NB, 256>>>();
    gather_kernel<<<dim3(NTOK, NB), 256>>>(f_ir, f_vis);
    base_kernel<<<9216, 256>>>(f_ir, f_vis, out);

    for (int mod = 0; mod < 2; mod++) {
        const float* const* Q = P + mod * 10;  // lng,lnb,wqkv,bqkv,wo,bo,w1,b1,w2,b2
        const float* X = (mod == 0) ? p_Xi : p_Xv;

        ln_kernel<<<dim3(288, NB), 256>>>(X, Q[0], Q[1], p_xn);
        mixer_gemm<0,false,false><<<dim3(36, 12, NB), 256>>>(p_xn, Q[2], Q[3], nullptr, p_qkv, 256, 768);
        flash_kernel<<<dim3(36, 4, NB), 256, 4*64*68*(int)sizeof(float)>>>();
        mixer_gemm<0,true ,false><<<dim3(36,  4, NB), 256>>>(p_attn, Q[4], Q[5], X, p_x1, 256, 256);
        ln_kernel<<<dim3(288, NB), 256>>>(p_x1, Q[0], Q[1], p_xn);
        mixer_gemm<1,false,false><<<dim3(36, 16, NB), 256>>>(p_xn, Q[6], Q[7], nullptr, p_hff, 256, 1024);
        if (mod == 0)
            mixer_gemm<0,true,false><<<dim3(36, 4, NB), 256>>>(p_hff, Q[8], Q[9], p_x1, p_mix, 1024, 256);
        else
            mixer_gemm<0,true,true ><<<dim3(36, 4, NB), 256>>>(p_hff, Q[8], Q[9], p_x1, p_mix, 1024, 256);
    }

    scatter_kernel<<<dim3(NTOK, NB), 256>>>(out);
}

// round 2
// speedup vs baseline: 2.3861x; 2.3861x over previous
#include <cuda_runtime.h>
#include <math.h>

#define NB   4
#define NTOK 2304
#define DIM  256
#define AGH  512

// ---------------- scratch (device globals; no allocation allowed) ----------------
__device__ float g_Xall[NB*NTOK*512];          // [b][n][c] c=0..255 ir, 256..511 vis
__device__ float g_h1[NB*NTOK*AGH];
__device__ float g_lf[NB*NTOK];
__device__ float g_maskf[NB*NTOK];
__device__ int   g_idx[NB*NTOK];
__device__ int   g_S[NB];
__device__ float g_X[2*NB*NTOK*DIM];           // compacted tokens, slot = mod*NB+b
__device__ float g_xn[2*NB*NTOK*DIM];
__device__ float g_qkv[2*NB*NTOK*3*DIM];
__device__ float g_attn[2*NB*NTOK*DIM];
__device__ float g_x1[2*NB*NTOK*DIM];
__device__ float g_hff[2*NB*NTOK*4*DIM];
__device__ float g_mix[2*NB*NTOK*DIM];

// ---------------- tf32 helpers --------------------------------------------------
__device__ __forceinline__ unsigned f2tf(float x) {
    unsigned u; asm("cvt.rna.tf32.f32 %0, %1;" : "=r"(u) : "f"(x)); return u;
}
__device__ __forceinline__ void mma8(float (&c)[4], const unsigned (&a)[4],
                                     const unsigned (&b)[2]) {
    asm volatile(
        "mma.sync.aligned.m16n8k8.row.col.f32.tf32.tf32.f32 "
        "{%0,%1,%2,%3}, {%4,%5,%6,%7}, {%8,%9}, {%0,%1,%2,%3};"
        : "+f"(c[0]), "+f"(c[1]), "+f"(c[2]), "+f"(c[3])
        : "r"(a[0]), "r"(a[1]), "r"(a[2]), "r"(a[3]), "r"(b[0]), "r"(b[1]));
}

// ---------------- transpose f -> token-major concat ----------------------------
__global__ void transpose_kernel(const float* __restrict__ f_ir,
                                 const float* __restrict__ f_vis)
{
    __shared__ float t[32][33];
    int b = blockIdx.z;
    int half = blockIdx.y >> 3;
    int c0 = (blockIdx.y & 7) * 32;
    int n0 = blockIdx.x * 32;
    const float* f = half ? f_vis : f_ir;
#pragma unroll
    for (int i = 0; i < 4; i++) {
        int c = c0 + threadIdx.y + i * 8;
        t[threadIdx.y + i*8][threadIdx.x] = f[((size_t)b*256 + c)*NTOK + n0 + threadIdx.x];
    }
    __syncthreads();
#pragma unroll
    for (int i = 0; i < 4; i++) {
        int n = n0 + threadIdx.y + i * 8;
        g_Xall[((size_t)b*NTOK + n)*512 + half*256 + c0 + threadIdx.x] = t[threadIdx.x][threadIdx.y + i*8];
    }
}

// ---------------- generic tf32 tensor-core GEMM --------------------------------
// C[z][row][n] = act( A[z][row][:] . W[mod][n][:] + bias[n] ) (+ R[z][row][n])
// block tile 128(M) x 64(N), K-chunk 32, 8 warps (4 M x 2 N), warp tile 32x32.
// HILO: 3xTF32 fp32-accurate path (agent).
template<int ACT, bool RES, bool USE_S, bool HILO>
__global__ void tgemm(const float* __restrict__ A,
                      const float* __restrict__ W0, const float* __restrict__ W1,
                      const float* __restrict__ bias0, const float* __restrict__ bias1,
                      const float* __restrict__ R, float* __restrict__ C,
                      int K, int N)
{
    int z = blockIdx.z;
    int b = z & (NB - 1);
    int S = USE_S ? g_S[b] : NTOK;
    int row0 = blockIdx.x * 128;
    if (row0 >= S) return;
    const float* W    = (z < NB) ? W0 : W1;
    const float* bias = (z < NB) ? bias0 : bias1;
    int n0 = blockIdx.y * 64;
    const float* Ab = A + (size_t)z * NTOK * K;
    float*       Cb = C + (size_t)z * NTOK * N;
    const float* Rb = RES ? (R + (size_t)z * NTOK * N) : nullptr;

    extern __shared__ unsigned sh[];
    unsigned* As_hi = sh;                   // 128*36
    unsigned* Ws_hi = sh + 128*36;          // 64*36
    unsigned* As_lo = HILO ? sh + 192*36 : nullptr;
    unsigned* Ws_lo = HILO ? sh + 320*36 : nullptr;

    int tid  = threadIdx.x;
    int warp = tid >> 5, lane = tid & 31;
    int g = lane >> 2, tig = lane & 3;
    int wm = warp >> 1, wn = warp & 1;

    float acc[2][4][4];
#pragma unroll
    for (int mi = 0; mi < 2; mi++)
#pragma unroll
        for (int ni = 0; ni < 4; ni++)
#pragma unroll
            for (int q = 0; q < 4; q++) acc[mi][ni][q] = 0.f;

    for (int k0 = 0; k0 < K; k0 += 32) {
        // load A tile 128x32
#pragma unroll
        for (int it = 0; it < 4; it++) {
            int lin = tid + it * 256;
            int r = lin >> 3, c4 = (lin & 7) * 4;
            int row = row0 + r;
            float4 v = make_float4(0.f, 0.f, 0.f, 0.f);
            if (row < S) v = *(const float4*)&Ab[(size_t)row * K + k0 + c4];
            uint4 hv;
            hv.x = f2tf(v.x); hv.y = f2tf(v.y); hv.z = f2tf(v.z); hv.w = f2tf(v.w);
            *(uint4*)&As_hi[r*36 + c4] = hv;
            if (HILO) {
                uint4 lv;
                lv.x = f2tf(v.x - __uint_as_float(hv.x));
                lv.y = f2tf(v.y - __uint_as_float(hv.y));
                lv.z = f2tf(v.z - __uint_as_float(hv.z));
                lv.w = f2tf(v.w - __uint_as_float(hv.w));
                *(uint4*)&As_lo[r*36 + c4] = lv;
            }
        }
        // load W tile 64x32
#pragma unroll
        for (int it = 0; it < 2; it++) {
            int lin = tid + it * 256;
            int r = lin >> 3, c4 = (lin & 7) * 4;
            float4 v = *(const float4*)&W[(size_t)(n0 + r) * K + k0 + c4];
            uint4 hv;
            hv.x = f2tf(v.x); hv.y = f2tf(v.y); hv.z = f2tf(v.z); hv.w = f2tf(v.w);
            *(uint4*)&Ws_hi[r*36 + c4] = hv;
            if (HILO) {
                uint4 lv;
                lv.x = f2tf(v.x - __uint_as_float(hv.x));
                lv.y = f2tf(v.y - __uint_as_float(hv.y));
                lv.z = f2tf(v.z - __uint_as_float(hv.z));
                lv.w = f2tf(v.w - __uint_as_float(hv.w));
                *(uint4*)&Ws_lo[r*36 + c4] = lv;
            }
        }
        __syncthreads();

#pragma unroll
        for (int ks = 0; ks < 4; ks++) {
            int base = ks * 8;
            unsigned a_hi[2][4], b_hi[4][2];
#pragma unroll
            for (int mi = 0; mi < 2; mi++) {
                int rb = wm*32 + mi*16;
                a_hi[mi][0] = As_hi[(rb + g    )*36 + base + tig];
                a_hi[mi][1] = As_hi[(rb + 8 + g)*36 + base + tig];
                a_hi[mi][2] = As_hi[(rb + g    )*36 + base + tig + 4];
                a_hi[mi][3] = As_hi[(rb + 8 + g)*36 + base + tig + 4];
            }
#pragma unroll
            for (int ni = 0; ni < 4; ni++) {
                int nb = wn*32 + ni*8;
                b_hi[ni][0] = Ws_hi[(nb + g)*36 + base + tig];
                b_hi[ni][1] = Ws_hi[(nb + g)*36 + base + tig + 4];
            }
            if (HILO) {
                unsigned a_lo[2][4], b_lo[4][2];
#pragma unroll
                for (int mi = 0; mi < 2; mi++) {
                    int rb = wm*32 + mi*16;
                    a_lo[mi][0] = As_lo[(rb + g    )*36 + base + tig];
                    a_lo[mi][1] = As_lo[(rb + 8 + g)*36 + base + tig];
                    a_lo[mi][2] = As_lo[(rb + g    )*36 + base + tig + 4];
                    a_lo[mi][3] = As_lo[(rb + 8 + g)*36 + base + tig + 4];
                }
#pragma unroll
                for (int ni = 0; ni < 4; ni++) {
                    int nb = wn*32 + ni*8;
                    b_lo[ni][0] = Ws_lo[(nb + g)*36 + base + tig];
                    b_lo[ni][1] = Ws_lo[(nb + g)*36 + base + tig + 4];
                }
#pragma unroll
                for (int mi = 0; mi < 2; mi++)
#pragma unroll
                    for (int ni = 0; ni < 4; ni++) {
                        mma8(acc[mi][ni], a_hi[mi], b_lo[ni]);
                        mma8(acc[mi][ni], a_lo[mi], b_hi[ni]);
                        mma8(acc[mi][ni], a_hi[mi], b_hi[ni]);
                    }
            } else {
#pragma unroll
                for (int mi = 0; mi < 2; mi++)
#pragma unroll
                    for (int ni = 0; ni < 4; ni++)
                        mma8(acc[mi][ni], a_hi[mi], b_hi[ni]);
            }
        }
        __syncthreads();
    }

    // epilogue
#pragma unroll
    for (int mi = 0; mi < 2; mi++) {
#pragma unroll
        for (int ni = 0; ni < 4; ni++) {
            int cb = n0 + wn*32 + ni*8 + 2*tig;
            float2 bb = *(const float2*)&bias[cb];
#pragma unroll
            for (int h = 0; h < 2; h++) {
                int row = row0 + wm*32 + mi*16 + g + h*8;
                if (row >= S) continue;
                float v0 = acc[mi][ni][h*2 + 0] + bb.x;
                float v1 = acc[mi][ni][h*2 + 1] + bb.y;
                if (ACT == 1) {
                    v0 = 0.5f * v0 * (1.f + erff(v0 * 0.70710678118654752f));
                    v1 = 0.5f * v1 * (1.f + erff(v1 * 0.70710678118654752f));
                } else if (ACT == 2) {
                    v0 = v0 / (1.f + expf(-v0));
                    v1 = v1 / (1.f + expf(-v1));
                }
                if (RES) {
                    float2 rr = *(const float2*)&Rb[(size_t)row * N + cb];
                    v0 += rr.x; v1 += rr.y;
                }
                *(float2*)&Cb[(size_t)row * N + cb] = make_float2(v0, v1);
            }
        }
    }
}

// ---------------- logits: lf[p] = h1[p]·aw2 + ab2 (warp per pixel) --------------
__global__ void logits_kernel(const float* __restrict__ aw2,
                              const float* __restrict__ ab2)
{
    int p = blockIdx.x * 8 + (threadIdx.x >> 5);
    int lane = threadIdx.x & 31;
    const float* h = g_h1 + (size_t)p * AGH;
    float s = 0.f;
#pragma unroll
    for (int j = 0; j < 16; j++) s += h[lane + 32*j] * aw2[lane + 32*j];
#pragma unroll
    for (int o = 16; o > 0; o >>= 1) s += __shfl_xor_sync(0xffffffffu, s, o);
    if (lane == 0) g_lf[p] = s + ab2[0];
}

// ---------------- selection + top-64 fallback + compaction ----------------------
__global__ void select_kernel()
{
    __shared__ float vals[NTOK];
    __shared__ int   sels[NTOK];
    __shared__ int   cnts[256];
    __shared__ float rv[256];
    __shared__ int   ri[256];
    __shared__ int   offs[257];
    int b = blockIdx.x, tid = threadIdx.x;

    int localc = 0;
    for (int n = tid; n < NTOK; n += 256) {
        float v = g_lf[b*NTOK + n];
        vals[n] = v;
        int s = (v > 0.f) ? 1 : 0;
        sels[n] = s;
        g_maskf[b*NTOK + n] = s ? 1.f : 0.f;
        localc += s;
    }
    cnts[tid] = localc;
    __syncthreads();
    for (int o = 128; o > 0; o >>= 1) {
        if (tid < o) cnts[tid] += cnts[tid + o];
        __syncthreads();
    }
    int count = cnts[0];
    __syncthreads();

    if (count < 64) {
        for (int n = tid; n < NTOK; n += 256) sels[n] = 0;
        __syncthreads();
        for (int iter = 0; iter < 64; iter++) {
            float bv = -1e38f; int bi = NTOK;
            for (int n = tid; n < NTOK; n += 256)
                if (!sels[n] && vals[n] > bv) { bv = vals[n]; bi = n; }
            rv[tid] = bv; ri[tid] = bi;
            __syncthreads();
            for (int o = 128; o > 0; o >>= 1) {
                if (tid < o) {
                    if (rv[tid+o] > rv[tid] ||
                        (rv[tid+o] == rv[tid] && ri[tid+o] < ri[tid])) {
                        rv[tid] = rv[tid+o]; ri[tid] = ri[tid+o];
                    }
                }
                __syncthreads();
            }
            if (tid == 0) sels[ri[0]] = 1;
            __syncthreads();
        }
    }

    int base = tid * 9;
    int lc = 0;
    for (int k = 0; k < 9; k++) lc += sels[base + k];
    cnts[tid] = lc;
    __syncthreads();
    if (tid == 0) {
        int run = 0;
        for (int i = 0; i < 256; i++) { offs[i] = run; run += cnts[i]; }
        offs[256] = run;
        g_S[b] = run;
    }
    __syncthreads();
    int pos = offs[tid];
    for (int k = 0; k < 9; k++)
        if (sels[base + k]) g_idx[b*NTOK + pos++] = base + k;
}

// ---------------- gather compacted tokens (both modules) ------------------------
__global__ void gather_kernel()
{
    int b = blockIdx.y, s = blockIdx.x;
    if (s >= g_S[b]) return;
    int n = g_idx[b*NTOK + s];
    int c = threadIdx.x;
    const float* src = g_Xall + ((size_t)b*NTOK + n)*512;
    g_X[((size_t)b*NTOK + s)*DIM + c]            = src[c];
    g_X[((size_t)(NB + b)*NTOK + s)*DIM + c]     = src[256 + c];
}

// ---------------- LayerNorm (warp per token) ------------------------------------
__global__ void ln_kernel(const float* __restrict__ X,
                          const float* __restrict__ g0, const float* __restrict__ b0_,
                          const float* __restrict__ g1, const float* __restrict__ b1_,
                          float* __restrict__ O)
{
    int z = blockIdx.y;
    int b = z & (NB - 1);
    int t = blockIdx.x * 8 + (threadIdx.x >> 5);
    if (t >= g_S[b]) return;
    const float* gg = (z < NB) ? g0 : g1;
    const float* bb = (z < NB) ? b0_ : b1_;
    int lane = threadIdx.x & 31;
    const float* x = X + ((size_t)z*NTOK + t)*DIM;
    float v[8];
    float s = 0.f;
#pragma unroll
    for (int j = 0; j < 8; j++) { v[j] = x[lane + 32*j]; s += v[j]; }
#pragma unroll
    for (int o = 16; o > 0; o >>= 1) s += __shfl_xor_sync(0xffffffffu, s, o);
    float mean = s * (1.f/256.f);
    float vs = 0.f;
#pragma unroll
    for (int j = 0; j < 8; j++) { float d = v[j] - mean; vs += d*d; }
#pragma unroll
    for (int o = 16; o > 0; o >>= 1) vs += __shfl_xor_sync(0xffffffffu, vs, o);
    float rstd = rsqrtf(vs * (1.f/256.f) + 1e-5f);
    float* o = O + ((size_t)z*NTOK + t)*DIM;
#pragma unroll
    for (int j = 0; j < 8; j++) {
        int c = lane + 32*j;
        o[c] = (v[j] - mean) * rstd * gg[c] + bb[c];
    }
}

// ---------------- flash attention, tf32 mma (dh=64, 4 heads) --------------------
__global__ void flash_kernel()
{
    extern __shared__ unsigned fsm[];
    unsigned* Qs  = fsm;                 // [64][68] tf32
    unsigned* Ks  = fsm + 64*68;         // [64][68] tf32
    unsigned* Vst = fsm + 2*64*68;       // [d][key] tf32 (transposed)
    float*    Ss  = (float*)(fsm + 3*64*68);   // [q][key] scores then p(tf32)
    unsigned* Psu = fsm + 3*64*68;
    __shared__ float m_s[64], l_s[64], al_s[64];

    int z = blockIdx.z;
    int b = z & (NB - 1);
    int h = blockIdx.y;
    int S = g_S[b];
    int qb = blockIdx.x * 64;
    if (qb >= S) return;
    int tid = threadIdx.x;
    int warp = tid >> 5, lane = tid & 31;
    int g = lane >> 2, tig = lane & 3;
    int wm = warp >> 1, wn = warp & 1;
    const float* qkvb = g_qkv + (size_t)z * NTOK * 768;

    // load Q tile
#pragma unroll
    for (int it = 0; it < 4; it++) {
        int lin = tid + it * 256;
        int r = lin >> 4, c4 = (lin & 15) * 4;
        int t = qb + r;
        float4 v = make_float4(0.f, 0.f, 0.f, 0.f);
        if (t < S) v = *(const float4*)&qkvb[(size_t)t*768 + h*64 + c4];
        uint4 hv; hv.x = f2tf(v.x); hv.y = f2tf(v.y); hv.z = f2tf(v.z); hv.w = f2tf(v.w);
        *(uint4*)&Qs[r*68 + c4] = hv;
    }
    if (tid < 64) { m_s[tid] = -1e30f; l_s[tid] = 0.f; }

    float oacc[4][4];
#pragma unroll
    for (int ni = 0; ni < 4; ni++)
#pragma unroll
        for (int q = 0; q < 4; q++) oacc[ni][q] = 0.f;

    for (int kb = 0; kb < S; kb += 64) {
        __syncthreads();
        // load K tile
#pragma unroll
        for (int it = 0; it < 4; it++) {
            int lin = tid + it * 256;
            int r = lin >> 4, c4 = (lin & 15) * 4;
            int t = kb + r;
            float4 v = make_float4(0.f, 0.f, 0.f, 0.f);
            if (t < S) v = *(const float4*)&qkvb[(size_t)t*768 + 256 + h*64 + c4];
            uint4 hv; hv.x = f2tf(v.x); hv.y = f2tf(v.y); hv.z = f2tf(v.z); hv.w = f2tf(v.w);
            *(uint4*)&Ks[r*68 + c4] = hv;
        }
        // load V transposed: Vst[d][key]
#pragma unroll
        for (int it = 0; it < 16; it++) {
            int lin = tid + it * 256;
            int d = lin & 63, tt = lin >> 6;
            int t = kb + tt;
            float v = (t < S) ? qkvb[(size_t)t*768 + 512 + h*64 + d] : 0.f;
            Vst[d*68 + tt] = f2tf(v);
        }
        __syncthreads();

        // S = Q K^T (warp tile m16 x n32)
        float sacc[4][4];
#pragma unroll
        for (int ni = 0; ni < 4; ni++)
#pragma unroll
            for (int q = 0; q < 4; q++) sacc[ni][q] = 0.f;
#pragma unroll
        for (int ks = 0; ks < 8; ks++) {
            int base = ks * 8;
            unsigned a[4];
            int rb = wm * 16;
            a[0] = Qs[(rb + g    )*68 + base + tig];
            a[1] = Qs[(rb + 8 + g)*68 + base + tig];
            a[2] = Qs[(rb + g    )*68 + base + tig + 4];
            a[3] = Qs[(rb + 8 + g)*68 + base + tig + 4];
#pragma unroll
            for (int ni = 0; ni < 4; ni++) {
                int key = wn*32 + ni*8 + g;
                unsigned bf[2];
                bf[0] = Ks[key*68 + base + tig];
                bf[1] = Ks[key*68 + base + tig + 4];
                mma8(sacc[ni], a, bf);
            }
        }
        // scale + mask + store scores
#pragma unroll
        for (int ni = 0; ni < 4; ni++) {
            int kcol = wn*32 + ni*8 + 2*tig;
            int q0 = wm*16 + g;
            float s0 = sacc[ni][0] * 0.125f, s1 = sacc[ni][1] * 0.125f;
            float s2 = sacc[ni][2] * 0.125f, s3 = sacc[ni][3] * 0.125f;
            if (kb + kcol     >= S) { s0 = -1e30f; s2 = -1e30f; }
            if (kb + kcol + 1 >= S) { s1 = -1e30f; s3 = -1e30f; }
            *(float2*)&Ss[q0*68 + kcol]       = make_float2(s0, s1);
            *(float2*)&Ss[(q0+8)*68 + kcol]   = make_float2(s2, s3);
        }
        __syncthreads();

        // online softmax (4 threads per row)
        {
            int row = tid >> 2, sub = tid & 3;
            float* Sr = Ss + row*68;
            float vv[16];
            float rm = -1e30f;
#pragma unroll
            for (int j = 0; j < 16; j++) { vv[j] = Sr[sub + 4*j]; rm = fmaxf(rm, vv[j]); }
            rm = fmaxf(rm, __shfl_xor_sync(0xffffffffu, rm, 1));
            rm = fmaxf(rm, __shfl_xor_sync(0xffffffffu, rm, 2));
            float mo = m_s[row];
            float mn = fmaxf(mo, rm);
            float rs = 0.f;
#pragma unroll
            for (int j = 0; j < 16; j++) {
                float p = __expf(vv[j] - mn);
                rs += p;
                Sr[sub + 4*j] = __uint_as_float(f2tf(p));
            }
            rs += __shfl_xor_sync(0xffffffffu, rs, 1);
            rs += __shfl_xor_sync(0xffffffffu, rs, 2);
            if (sub == 0) {
                float al = __expf(mo - mn);
                l_s[row] = l_s[row] * al + rs;
                m_s[row] = mn;
                al_s[row] = al;
            }
        }
        __syncthreads();

        // rescale O accumulators
        {
            float al0 = al_s[wm*16 + g];
            float al1 = al_s[wm*16 + 8 + g];
#pragma unroll
            for (int ni = 0; ni < 4; ni++) {
                oacc[ni][0] *= al0; oacc[ni][1] *= al0;
                oacc[ni][2] *= al1; oacc[ni][3] *= al1;
            }
        }

        // O += P V (A = P rows q, B = Vst[d][key])
#pragma unroll
        for (int ks = 0; ks < 8; ks++) {
            int base = ks * 8;
            unsigned a[4];
            int rb = wm * 16;
            a[0] = Psu[(rb + g    )*68 + base + tig];
            a[1] = Psu[(rb + 8 + g)*68 + base + tig];
            a[2] = Psu[(rb + g    )*68 + base + tig + 4];
            a[3] = Psu[(rb + 8 + g)*68 + base + tig + 4];
#pragma unroll
            for (int ni = 0; ni < 4; ni++) {
                int d = wn*32 + ni*8 + g;
                unsigned bf[2];
                bf[0] = Vst[d*68 + base + tig];
                bf[1] = Vst[d*68 + base + tig + 4];
                mma8(oacc[ni], a, bf);
            }
        }
    }

    // final normalize + store
    {
        int q0 = wm*16 + g;
        float il0 = 1.f / l_s[q0];
        float il1 = 1.f / l_s[q0 + 8];
        int t0 = qb + q0, t1 = qb + q0 + 8;
        float* ab = g_attn + (size_t)z * NTOK * DIM;
#pragma unroll
        for (int ni = 0; ni < 4; ni++) {
            int d = h*64 + wn*32 + ni*8 + 2*tig;
            if (t0 < S)
                *(float2*)&ab[(size_t)t0*DIM + d] = make_float2(oacc[ni][0]*il0, oacc[ni][1]*il0);
            if (t1 < S)
                *(float2*)&ab[(size_t)t1*DIM + d] = make_float2(oacc[ni][2]*il1, oacc[ni][3]*il1);
        }
    }
}

// ---------------- base canvas + final scatter ----------------------------------
__global__ void base_kernel(const float* __restrict__ a, const float* __restrict__ c,
                            float* __restrict__ out)
{
    int i = blockIdx.x * 256 + threadIdx.x;
    out[i] = a[i] + c[i];
}

__global__ void scatter_kernel(float* __restrict__ out)
{
    int b = blockIdx.y, s = blockIdx.x;
    if (s >= g_S[b]) return;
    int n = g_idx[b*NTOK + s];
    int c = threadIdx.x;
    float v = (g_mix[((size_t)b*NTOK + s)*DIM + c] +
               g_mix[((size_t)(NB + b)*NTOK + s)*DIM + c]) * g_maskf[b*NTOK + n];
    out[((size_t)b*DIM + c)*NTOK + n] = v;
}

// ---------------- host ----------------------------------------------------------
#define GETSYM(ptr, sym) cudaGetSymbolAddress((void**)&(ptr), sym)

extern "C" void kernel_launch(void* const* d_in, const int* in_sizes, int n_in,
                              void* d_out, int out_size)
{
    const float* f_ir  = (const float*)d_in[0];
    const float* f_vis = (const float*)d_in[1];
    const float* aw1   = (const float*)d_in[2];
    const float* ab1   = (const float*)d_in[3];
    const float* aw2   = (const float*)d_in[4];
    const float* ab2   = (const float*)d_in[5];
    const float* P[20];
    for (int i = 0; i < 20; i++) P[i] = (const float*)d_in[6 + i];
    // P layout: [ir: lng,lnb,wqkv,bqkv,wo,bo,w1,b1,w2,b2][vis: same]
    float* out = (float*)d_out;

    float *p_Xall, *p_h1, *p_X, *p_xn, *p_qkv, *p_attn, *p_x1, *p_hff, *p_mix;
    GETSYM(p_Xall, g_Xall); GETSYM(p_h1, g_h1); GETSYM(p_X, g_X);
    GETSYM(p_xn, g_xn);     GETSYM(p_qkv, g_qkv); GETSYM(p_attn, g_attn);
    GETSYM(p_x1, g_x1);     GETSYM(p_hff, g_hff); GETSYM(p_mix, g_mix);

    const int SM1 = 192*36*4;      // 27648 B : single tf32
    const int SM3 = 384*36*4;      // 55296 B : 3xTF32
    const int SMF = 4*64*68*4;     // 69632 B : flash

    cudaFuncSetAttribute(tgemm<2,false,false,true>, cudaFuncAttributeMaxDynamicSharedMemorySize, SM3);
    cudaFuncSetAttribute(tgemm<0,false,true,false>, cudaFuncAttributeMaxDynamicSharedMemorySize, SM1);
    cudaFuncSetAttribute(tgemm<0,true ,true,false>, cudaFuncAttributeMaxDynamicSharedMemorySize, SM1);
    cudaFuncSetAttribute(tgemm<1,false,true,false>, cudaFuncAttributeMaxDynamicSharedMemorySize, SM1);
    cudaFuncSetAttribute(flash_kernel, cudaFuncAttributeMaxDynamicSharedMemorySize, SMF);

    transpose_kernel<<<dim3(72, 16, NB), dim3(32, 8)>>>(f_ir, f_vis);
    // agent: 3xTF32 (fp32-accurate; feeds mask sign decisions), silu
    tgemm<2,false,false,true><<<dim3(18, 8, NB), 256, SM3>>>(
        p_Xall, aw1, aw1, ab1, ab1, nullptr, p_h1, 512, 512);
    logits_kernel<<<1152, 256>>>(aw2, ab2);
    select_kernel<<<NB, 256>>>();
    gather_kernel<<<dim3(NTOK, NB), 256>>>();
    base_kernel<<<9216, 256>>>(f_ir, f_vis, out);

    // fused ir+vis mixer pipeline: z = mod*NB + b (8 slots)
    ln_kernel<<<dim3(288, 8), 256>>>(p_X, P[0], P[1], P[10], P[11], p_xn);
    tgemm<0,false,true,false><<<dim3(18, 12, 8), 256, SM1>>>(
        p_xn, P[2], P[12], P[3], P[13], nullptr, p_qkv, 256, 768);
    flash_kernel<<<dim3(36, 4, 8), 256, SMF>>>();
    tgemm<0,true,true,false><<<dim3(18, 4, 8), 256, SM1>>>(
        p_attn, P[4], P[14], P[5], P[15], p_X, p_x1, 256, 256);
    ln_kernel<<<dim3(288, 8), 256>>>(p_x1, P[0], P[1], P[10], P[11], p_xn);
    tgemm<1,false,true,false><<<dim3(18, 16, 8), 256, SM1>>>(
        p_xn, P[6], P[16], P[7], P[17], nullptr, p_hff, 256, 1024);
    tgemm<0,true,true,false><<<dim3(18, 4, 8), 256, SM1>>>(
        p_hff, P[8], P[18], P[9], P[19], p_x1, p_mix, 1024, 256);

    scatter_kernel<<<dim3(NTOK, NB), 256>>>(out);
}